// round 8
// baseline (speedup 1.0000x reference)
#include <cuda_runtime.h>
#include <cstdint>

#define NH 12
#define DH 64
#define SEQ 512
#define DM 768
#define MAXB 32

typedef unsigned long long u64;

// ============================ PTX helpers ============================
__device__ __forceinline__ float tf32r(float x) {
    float r; asm("cvt.rna.tf32.f32 %0, %1;" : "=f"(r) : "f"(x)); return r;
}
__device__ __forceinline__ void mma8(float* c, const uint32_t* a, const uint32_t* b) {
    asm volatile(
        "mma.sync.aligned.m16n8k8.row.col.f32.tf32.tf32.f32 "
        "{%0,%1,%2,%3}, {%4,%5,%6,%7}, {%8,%9}, {%0,%1,%2,%3};"
        : "+f"(c[0]), "+f"(c[1]), "+f"(c[2]), "+f"(c[3])
        : "r"(a[0]), "r"(a[1]), "r"(a[2]), "r"(a[3]), "r"(b[0]), "r"(b[1]));
}
__device__ __forceinline__ uint32_t fbits(float x) { return __float_as_uint(x); }
__device__ __forceinline__ uint32_t smem_u32(const void* p) {
    uint32_t a;
    asm("{ .reg .u64 t; cvta.to.shared.u64 t, %1; cvt.u32.u64 %0, t; }" : "=r"(a) : "l"(p));
    return a;
}
__device__ __forceinline__ void cpa16(uint32_t s, const float* g) {
    asm volatile("cp.async.cg.shared.global [%0], [%1], 16;" :: "r"(s), "l"(g));
}
__device__ __forceinline__ void cpa_commit() {
    asm volatile("cp.async.commit_group;" ::: "memory");
}
template<int N>
__device__ __forceinline__ void cpa_wait() {
    asm volatile("cp.async.wait_group %0;" :: "n"(N) : "memory");
}

// d-perm within 8-groups: swap so (k, k+4) become adjacent
__device__ __forceinline__ int dperm(int d) {
    return (d & ~7) | (((d & 3) << 1) | ((d >> 2) & 1));
}

// ============================ device scratch ============================
__device__ float g_q[(size_t)MAXB * NH * SEQ * DH];     // tf32, d-permuted
__device__ float g_k[(size_t)MAXB * NH * SEQ * DH];     // tf32, d-permuted
__device__ float g_v[(size_t)MAXB * NH * SEQ * DH];     // tf32, natural d
__device__ float g_aht[(size_t)DM * MAXB * SEQ];        // hidden^T [k][m_perm], tf32
__device__ float g_wth[(size_t)3 * DM * DM];            // W^T [mat][n][k], tf32

// ---------------------------------------------------------------------------
__global__ void htrans_kernel(const float* __restrict__ h, int M) {
    __shared__ float t[32][33];
    const int m0 = blockIdx.x * 32, k0 = blockIdx.y * 32;
    const int tx = threadIdx.x, ty = threadIdx.y;
#pragma unroll
    for (int j = 0; j < 32; j += 8)
        t[ty + j][tx] = tf32r(h[(size_t)(m0 + ty + j) * DM + k0 + tx]);
    __syncthreads();
    const int m = m0 + tx;
    const int mp = (m & ~15) | (((m & 7) << 1) | ((m >> 3) & 1));
#pragma unroll
    for (int j = 0; j < 32; j += 8)
        g_aht[(size_t)(k0 + ty + j) * M + mp] = t[tx][ty + j];
}

__global__ void wsplit_kernel(const float* __restrict__ Wq,
                              const float* __restrict__ Wk,
                              const float* __restrict__ Wv) {
    __shared__ float th[32][33];
    int mat = blockIdx.z;
    const float* W = (mat == 0) ? Wq : ((mat == 1) ? Wk : Wv);
    int k0 = blockIdx.y * 32, n0 = blockIdx.x * 32;
    int tx = threadIdx.x, ty = threadIdx.y;
#pragma unroll
    for (int j = 0; j < 32; j += 8)
        th[ty + j][tx] = tf32r(W[(size_t)(k0 + ty + j) * DM + n0 + tx]);
    __syncthreads();
    float* oh = g_wth + (size_t)mat * DM * DM;
#pragma unroll
    for (int j = 0; j < 32; j += 8)
        oh[(size_t)(n0 + ty + j) * DM + k0 + tx] = th[tx][ty + j];
}

// ---------------------------------------------------------------------------
// Unified QKV GEMM, single-term tf32, cp.async 3-stage pipeline.
// CTA tile 128(m) x 256(n); 8 warps as 2(m) x 4(n); warp 64x64.
// K-chunk 32 (4 ksteps). Epilogue: +bias; Q/K tf32+dperm; V tf32.
// ---------------------------------------------------------------------------
#define ASTAGE_F 4096            // 32 k-rows * 128 m floats (swizzled)
#define BSTAGE_F (256 * 36)      // 256 n-rows * 32 k (pad 36)
#define NSTG 3
#define GEMM_SMEM ((NSTG * (ASTAGE_F + BSTAGE_F)) * 4)   // 159744 B

__global__ __launch_bounds__(256, 1) void qkv_gemm_kernel(
    const float* __restrict__ bq, const float* __restrict__ bk,
    const float* __restrict__ bv, int M)
{
    extern __shared__ float sm[];
    float* Bbase = sm + NSTG * ASTAGE_F;

    const int tid  = threadIdx.x;
    const int lane = tid & 31;
    const int wid  = tid >> 5;
    const int wm   = wid >> 2;       // 0..1 -> 64 m-rows
    const int wn   = wid & 3;        // 0..3 -> 64 n-cols
    const int lr   = lane >> 2;
    const int lc   = lane & 3;

    const int m0  = blockIdx.x * 128;
    const int yb  = blockIdx.y;      // 0..8
    const int mat = yb / 3;
    const int n0  = (yb % 3) * 256;

    const float* Wh = g_wth + (size_t)mat * DM * DM + (size_t)n0 * DM;

    // A load mapping: k-row tid>>3, m-seg (tid&7)*16
    const int ak   = tid >> 3;
    const int ams  = (tid & 7) * 16;
    const float* gA = g_aht + (size_t)ak * M + m0 + ams;
    // B load mapping: one n-row per thread (32 floats = 8 cpa16)
    const float* gB = Wh + (size_t)tid * DM;

    const uint32_t sbA = smem_u32(sm);
    const uint32_t sbB = smem_u32(Bbase);
    const uint32_t aXor = (uint32_t)((ak & 3) << 1);
    const uint32_t aRow = (uint32_t)ak * 512;
    const uint32_t bOff = (uint32_t)(tid * 36) * 4;

#define ISSUE(ch, st)                                                         \
    do {                                                                      \
        const float* _a = gA + (size_t)(ch) * 32 * M;                         \
        const float* _b = gB + (ch) * 32;                                     \
        uint32_t _sa = sbA + (st) * (ASTAGE_F * 4) + aRow;                    \
        uint32_t _sb = sbB + (st) * (BSTAGE_F * 4) + bOff;                    \
        _Pragma("unroll")                                                     \
        for (int _i = 0; _i < 4; _i++) {                                      \
            uint32_t _blk = (uint32_t)((ams >> 2) + _i) ^ aXor;               \
            cpa16(_sa + _blk * 16, _a + _i * 4);                              \
        }                                                                     \
        _Pragma("unroll")                                                     \
        for (int _i = 0; _i < 8; _i++)                                        \
            cpa16(_sb + _i * 16, _b + _i * 4);                                \
    } while (0)

    float c[4][8][4];
#pragma unroll
    for (int i = 0; i < 4; i++)
#pragma unroll
        for (int j = 0; j < 8; j++)
#pragma unroll
            for (int q = 0; q < 4; q++) c[i][j][q] = 0.0f;

    const int NCH = DM / 32;   // 24

#pragma unroll
    for (int p = 0; p < NSTG - 1; p++) {
        ISSUE(p, p);
        cpa_commit();
    }

    for (int ch = 0; ch < NCH; ch++) {
        const int pre = ch + NSTG - 1;
        if (pre < NCH) ISSUE(pre, pre % NSTG);
        cpa_commit();
        cpa_wait<NSTG - 1>();
        __syncthreads();

        const int st = ch % NSTG;
        const float* As = sm + st * ASTAGE_F;
        const float* Bs = Bbase + st * BSTAGE_F;

#pragma unroll
        for (int ks = 0; ks < 4; ks++) {
            const int kc = ks * 8;
            uint32_t ah[4][4];
#pragma unroll
            for (int mt = 0; mt < 4; mt++) {
                const int wl = wm * 64 + mt * 16;
                const uint32_t bXor = (uint32_t)(lc << 1);
                const uint32_t blk = (uint32_t)((wl >> 2) + (lr >> 1)) ^ bXor;
                const uint32_t fo  = (uint32_t)((lr & 1) * 2);
                float2 p01 = *(const float2*)(As + (kc + lc) * 128 + blk * 4 + fo);
                float2 p23 = *(const float2*)(As + (kc + 4 + lc) * 128 + blk * 4 + fo);
                ah[mt][0] = fbits(p01.x); ah[mt][1] = fbits(p01.y);
                ah[mt][2] = fbits(p23.x); ah[mt][3] = fbits(p23.y);
            }
            uint32_t bh[8][2];
#pragma unroll
            for (int nt = 0; nt < 8; nt++) {
                const int nb = wn * 64 + nt * 8;
                bh[nt][0] = fbits(Bs[(nb + lr) * 36 + kc + lc]);
                bh[nt][1] = fbits(Bs[(nb + lr) * 36 + kc + 4 + lc]);
            }
#pragma unroll
            for (int mt = 0; mt < 4; mt++)
#pragma unroll
                for (int nt = 0; nt < 8; nt++)
                    mma8(c[mt][nt], ah[mt], bh[nt]);
        }
        __syncthreads();
    }
#undef ISSUE

    // epilogue: Q/K -> tf32 + d-perm scatter; V -> tf32, natural layout
    const float* bias = (mat == 0) ? bq : ((mat == 1) ? bk : bv);
    float* dst        = (mat == 0) ? g_q : ((mat == 1) ? g_k : g_v);
    const bool rqk    = (mat != 2);
#pragma unroll
    for (int mt = 0; mt < 4; mt++) {
        const int m = m0 + wm * 64 + mt * 16 + lr;
#pragma unroll
        for (int nt = 0; nt < 8; nt++) {
            const int n = n0 + wn * 64 + nt * 8 + 2 * lc;
            const int hh = n >> 6, d = n & 63;
            const float b0 = bias[n], b1 = bias[n + 1];
#pragma unroll
            for (int half = 0; half < 2; half++) {
                const int mm = m + half * 8;
                const int bi = mm >> 9, srow = mm & 511;
                float v0 = tf32r(c[mt][nt][half * 2 + 0] + b0);
                float v1 = tf32r(c[mt][nt][half * 2 + 1] + b1);
                float* o = dst + (((size_t)(bi * NH + hh)) * SEQ + srow) * DH;
                if (rqk) {
                    o[dperm(d)]     = v0;
                    o[dperm(d + 1)] = v1;
                } else {
                    *(float2*)(o + d) = make_float2(v0, v1);
                }
            }
        }
    }
}

// ---------------------------------------------------------------------------
// Power-law attention (unchanged from R7): q-tile 128, key-tile 32,
// cp.async double-buffered K/V, LDS.64 fragments, mask in phase-2 B-frags.
// ---------------------------------------------------------------------------
#define KT 32
#define PADQ 72
#define PADKV 72
#define PADU 36
#define QS_F (128 * PADQ)
#define KBUF_F (KT * PADKV)
#define ATTN_SMEM ((QS_F + 4 * KBUF_F + 128 * PADU + 512) * 4)

__global__ __launch_bounds__(256) void attn_kernel(
    const float* __restrict__ mask, float* __restrict__ out)
{
    extern __shared__ float sm[];
    float* Qs = sm;
    float* Ks = Qs + QS_F;
    float* Vs = Ks + 2 * KBUF_F;
    float* Us = Vs + 2 * KBUF_F;
    float* Ms = Us + 128 * PADU;

    const int b  = blockIdx.z;
    const int h  = blockIdx.y;
    const int qt = blockIdx.x * 128;

    const float* Qg = g_q + (((size_t)(b * NH + h)) * SEQ + qt) * DH;
    const float* Kg = g_k + ((size_t)(b * NH + h)) * SEQ * DH;
    const float* Vg = g_v + ((size_t)(b * NH + h)) * SEQ * DH;

    const int tid  = threadIdx.x;
    const int lane = tid & 31;
    const int wid  = tid >> 5;
    const int wm   = wid >> 1;
    const int wn   = wid & 1;
    const int lr   = lane >> 2;
    const int lc   = lane & 3;

    const int krow = tid >> 3;
    const int kseg = (tid & 7) * 8;
    const float* KgR = Kg + (size_t)krow * DH + kseg;
    const float* VgR = Vg + (size_t)krow * DH + kseg;
    const uint32_t sKs = smem_u32(Ks) + (uint32_t)(krow * PADKV + kseg) * 4;
    const uint32_t sVs = smem_u32(Vs) + (uint32_t)(krow * PADKV + kseg) * 4;

#define ISSKV(kt_, buf_)                                                      \
    do {                                                                      \
        const float* _k = KgR + (size_t)(kt_) * KT * DH;                      \
        const float* _v = VgR + (size_t)(kt_) * KT * DH;                      \
        uint32_t _ob = (uint32_t)(buf_) * (KBUF_F * 4);                       \
        cpa16(sKs + _ob, _k);      cpa16(sKs + _ob + 16, _k + 4);             \
        cpa16(sVs + _ob, _v);      cpa16(sVs + _ob + 16, _v + 4);             \
        cpa_commit();                                                         \
    } while (0)

    ISSKV(0, 0);

    {
        const int r = tid >> 1;
        const int sg = (tid & 1) * 32;
        const float* src = Qg + (size_t)r * DH + sg;
        float* dq = &Qs[r * PADQ + sg];
#pragma unroll
        for (int i = 0; i < 8; i++)
            *(float4*)(dq + i * 4) = *(const float4*)(src + i * 4);
    }
    *(float2*)&Ms[tid * 2] = *(const float2*)(mask + (size_t)b * SEQ + tid * 2);

    float o[2][4][4];
#pragma unroll
    for (int i = 0; i < 2; i++)
#pragma unroll
        for (int j = 0; j < 4; j++)
#pragma unroll
            for (int q = 0; q < 4; q++) o[i][j][q] = 0.0f;
    float den[2][2] = {{0.0f, 0.0f}, {0.0f, 0.0f}};

    const int NKT = SEQ / KT;

    for (int kt = 0; kt < NKT; kt++) {
        const int buf = kt & 1;
        if (kt + 1 < NKT) {
            ISSKV(kt + 1, buf ^ 1);
            cpa_wait<1>();
        } else {
            cpa_wait<0>();
        }
        __syncthreads();

        const float* Kb = Ks + buf * KBUF_F;
        const float* Vb = Vs + buf * KBUF_F;

        float s[2][2][4];
#pragma unroll
        for (int i = 0; i < 2; i++)
#pragma unroll
            for (int j = 0; j < 2; j++)
#pragma unroll
                for (int q = 0; q < 4; q++) s[i][j][q] = 0.0f;

#pragma unroll
        for (int ks = 0; ks < 8; ks++) {
            const int kc = ks * 8;
            uint32_t a[2][4];
#pragma unroll
            for (int mt = 0; mt < 2; mt++) {
                const int rb = wm * 32 + mt * 16;
                float2 p0 = *(const float2*)&Qs[(rb + lr) * PADQ + kc + 2 * lc];
                float2 p1 = *(const float2*)&Qs[(rb + lr + 8) * PADQ + kc + 2 * lc];
                a[mt][0] = fbits(p0.x); a[mt][1] = fbits(p1.x);
                a[mt][2] = fbits(p0.y); a[mt][3] = fbits(p1.y);
            }
            uint32_t bb[2][2];
#pragma unroll
            for (int nt = 0; nt < 2; nt++) {
                const int nb = wn * 16 + nt * 8;
                float2 q2 = *(const float2*)&Kb[(nb + lr) * PADKV + kc + 2 * lc];
                bb[nt][0] = fbits(q2.x); bb[nt][1] = fbits(q2.y);
            }
#pragma unroll
            for (int mt = 0; mt < 2; mt++)
#pragma unroll
                for (int nt = 0; nt < 2; nt++)
                    mma8(s[mt][nt], a[mt], bb[nt]);
        }
#pragma unroll
        for (int mt = 0; mt < 2; mt++) {
            const int rb = wm * 32 + mt * 16;
#pragma unroll
            for (int nt = 0; nt < 2; nt++) {
                const int cb = wn * 16 + nt * 8 + 2 * lc;
                float t0 = fmaf(s[mt][nt][0], 0.125f, 5.0f);
                float t1 = fmaf(s[mt][nt][1], 0.125f, 5.0f);
                float t2 = fmaf(s[mt][nt][2], 0.125f, 5.0f);
                float t3 = fmaf(s[mt][nt][3], 0.125f, 5.0f);
                *(float2*)&Us[(rb + lr) * PADU + cb] =
                    make_float2(tf32r(t0 * t0), tf32r(t1 * t1));
                *(float2*)&Us[(rb + lr + 8) * PADU + cb] =
                    make_float2(tf32r(t2 * t2), tf32r(t3 * t3));
            }
        }
        __syncthreads();

#pragma unroll
        for (int ks = 0; ks < 4; ks++) {
            const int kc = ks * 8;
            const float m0 = Ms[kt * KT + kc + lc];
            const float m1 = Ms[kt * KT + kc + 4 + lc];
            uint32_t a[2][4];
#pragma unroll
            for (int mt = 0; mt < 2; mt++) {
                const int rb = wm * 32 + mt * 16;
                float f0 = Us[(rb + lr) * PADU + kc + lc];
                float f1 = Us[(rb + lr + 8) * PADU + kc + lc];
                float f2 = Us[(rb + lr) * PADU + kc + 4 + lc];
                float f3 = Us[(rb + lr + 8) * PADU + kc + 4 + lc];
                den[mt][0] += f0 + f2;
                den[mt][1] += f1 + f3;
                a[mt][0] = fbits(f0); a[mt][1] = fbits(f1);
                a[mt][2] = fbits(f2); a[mt][3] = fbits(f3);
            }
            uint32_t bb[4][2];
#pragma unroll
            for (int nt = 0; nt < 4; nt++) {
                const int db = wn * 32 + nt * 8 + lr;
                bb[nt][0] = fbits(Vb[(kc + lc) * PADKV + db] * m0);
                bb[nt][1] = fbits(Vb[(kc + 4 + lc) * PADKV + db] * m1);
            }
#pragma unroll
            for (int mt = 0; mt < 2; mt++)
#pragma unroll
                for (int nt = 0; nt < 4; nt++)
                    mma8(o[mt][nt], a[mt], bb[nt]);
        }
        __syncthreads();
    }
#undef ISSKV

#pragma unroll
    for (int mt = 0; mt < 2; mt++)
#pragma unroll
        for (int j = 0; j < 2; j++) {
            float v = den[mt][j];
            v += __shfl_xor_sync(0xFFFFFFFFu, v, 1);
            v += __shfl_xor_sync(0xFFFFFFFFu, v, 2);
            den[mt][j] = v;
        }

#pragma unroll
    for (int mt = 0; mt < 2; mt++) {
        const float inv0 = 1.0f / (den[mt][0] + 1e-10f);
        const float inv1 = 1.0f / (den[mt][1] + 1e-10f);
        const int rb = qt + wm * 32 + mt * 16 + lr;
#pragma unroll
        for (int nt = 0; nt < 4; nt++) {
            const int d = wn * 32 + nt * 8 + 2 * lc;
            float* o0 = out + ((size_t)b * SEQ + rb) * DM + h * DH + d;
            float* o1 = out + ((size_t)b * SEQ + rb + 8) * DM + h * DH + d;
            *(float2*)o0 = make_float2(o[mt][nt][0] * inv0, o[mt][nt][1] * inv0);
            *(float2*)o1 = make_float2(o[mt][nt][2] * inv1, o[mt][nt][3] * inv1);
        }
    }
}

// ---------------------------------------------------------------------------
extern "C" void kernel_launch(void* const* d_in, const int* in_sizes, int n_in,
                              void* d_out, int out_size)
{
    const float* hidden = (const float*)d_in[0];
    const float* mask   = (const float*)d_in[1];
    const float* Wq     = (const float*)d_in[2];
    const float* bq     = (const float*)d_in[3];
    const float* Wk     = (const float*)d_in[4];
    const float* bk     = (const float*)d_in[5];
    const float* Wv     = (const float*)d_in[6];
    const float* bv     = (const float*)d_in[7];
    float* out = (float*)d_out;

    const int BS = in_sizes[1];
    const int B  = BS / SEQ;
    const int M  = BS;

    cudaFuncSetAttribute(qkv_gemm_kernel,
                         cudaFuncAttributeMaxDynamicSharedMemorySize, GEMM_SMEM);
    cudaFuncSetAttribute(attn_kernel,
                         cudaFuncAttributeMaxDynamicSharedMemorySize, ATTN_SMEM);

    dim3 gh(M / 32, DM / 32);
    htrans_kernel<<<gh, dim3(32, 8)>>>(hidden, M);

    dim3 gw(DM / 32, DM / 32, 3);
    wsplit_kernel<<<gw, dim3(32, 8)>>>(Wq, Wk, Wv);

    dim3 gm(M / 128, 9);
    qkv_gemm_kernel<<<gm, 256, GEMM_SMEM>>>(bq, bk, bv, M);

    dim3 g2(SEQ / 128, NH, B);
    attn_kernel<<<g2, 256, ATTN_SMEM>>>(mask, out);
}

// round 9
// speedup vs baseline: 1.1509x; 1.1509x over previous
#include <cuda_runtime.h>
#include <cstdint>

#define NH 12
#define DH 64
#define SEQ 512
#define DM 768
#define MAXB 32

typedef unsigned long long u64;

// ============================ PTX helpers ============================
__device__ __forceinline__ float tf32r(float x) {
    float r; asm("cvt.rna.tf32.f32 %0, %1;" : "=f"(r) : "f"(x)); return r;
}
__device__ __forceinline__ void mma8(float* c, const uint32_t* a, const uint32_t* b) {
    asm volatile(
        "mma.sync.aligned.m16n8k8.row.col.f32.tf32.tf32.f32 "
        "{%0,%1,%2,%3}, {%4,%5,%6,%7}, {%8,%9}, {%0,%1,%2,%3};"
        : "+f"(c[0]), "+f"(c[1]), "+f"(c[2]), "+f"(c[3])
        : "r"(a[0]), "r"(a[1]), "r"(a[2]), "r"(a[3]), "r"(b[0]), "r"(b[1]));
}
__device__ __forceinline__ uint32_t fbits(float x) { return __float_as_uint(x); }
__device__ __forceinline__ uint32_t smem_u32(const void* p) {
    uint32_t a;
    asm("{ .reg .u64 t; cvta.to.shared.u64 t, %1; cvt.u32.u64 %0, t; }" : "=r"(a) : "l"(p));
    return a;
}
__device__ __forceinline__ void cpa16(uint32_t s, const float* g) {
    asm volatile("cp.async.cg.shared.global [%0], [%1], 16;" :: "r"(s), "l"(g));
}
__device__ __forceinline__ void cpa_commit() {
    asm volatile("cp.async.commit_group;" ::: "memory");
}
template<int N>
__device__ __forceinline__ void cpa_wait() {
    asm volatile("cp.async.wait_group %0;" :: "n"(N) : "memory");
}

// d-perm within 8-groups: swap so (k, k+4) become adjacent
__device__ __forceinline__ int dperm(int d) {
    return (d & ~7) | (((d & 3) << 1) | ((d >> 2) & 1));
}

// ============================ device scratch ============================
__device__ float g_q[(size_t)MAXB * NH * SEQ * DH];     // tf32, d-permuted
__device__ float g_k[(size_t)MAXB * NH * SEQ * DH];     // tf32, d-permuted
__device__ float g_vt[(size_t)MAXB * NH * DH * SEQ];    // tf32, TRANSPOSED [d][s], mask folded
__device__ float g_aht[(size_t)DM * MAXB * SEQ];        // hidden^T [k][m_perm], tf32
__device__ float g_wth[(size_t)3 * DM * DM];            // W^T [mat][n][k], tf32

// ---------------------------------------------------------------------------
__global__ void htrans_kernel(const float* __restrict__ h, int M) {
    __shared__ float t[32][33];
    const int m0 = blockIdx.x * 32, k0 = blockIdx.y * 32;
    const int tx = threadIdx.x, ty = threadIdx.y;
#pragma unroll
    for (int j = 0; j < 32; j += 8)
        t[ty + j][tx] = tf32r(h[(size_t)(m0 + ty + j) * DM + k0 + tx]);
    __syncthreads();
    const int m = m0 + tx;
    const int mp = (m & ~15) | (((m & 7) << 1) | ((m >> 3) & 1));
#pragma unroll
    for (int j = 0; j < 32; j += 8)
        g_aht[(size_t)(k0 + ty + j) * M + mp] = t[tx][ty + j];
}

__global__ void wsplit_kernel(const float* __restrict__ Wq,
                              const float* __restrict__ Wk,
                              const float* __restrict__ Wv) {
    __shared__ float th[32][33];
    int mat = blockIdx.z;
    const float* W = (mat == 0) ? Wq : ((mat == 1) ? Wk : Wv);
    int k0 = blockIdx.y * 32, n0 = blockIdx.x * 32;
    int tx = threadIdx.x, ty = threadIdx.y;
#pragma unroll
    for (int j = 0; j < 32; j += 8)
        th[ty + j][tx] = tf32r(W[(size_t)(k0 + ty + j) * DM + n0 + tx]);
    __syncthreads();
    float* oh = g_wth + (size_t)mat * DM * DM;
#pragma unroll
    for (int j = 0; j < 32; j += 8)
        oh[(size_t)(n0 + ty + j) * DM + k0 + tx] = th[tx][ty + j];
}

// ---------------------------------------------------------------------------
// Unified QKV GEMM (R7 config: CTA 128x128, 8 warps 2m x 4n, NSTG=3).
// Epilogue: Q/K tf32+dperm scatter; V -> tf32, mask-multiplied, TRANSPOSED.
// ---------------------------------------------------------------------------
#define ASTAGE_F 4096
#define BSTAGE_F (128 * 36)
#define NSTG 3
#define GEMM_SMEM ((NSTG * (ASTAGE_F + BSTAGE_F)) * 4)

__global__ __launch_bounds__(256) void qkv_gemm_kernel(
    const float* __restrict__ bq, const float* __restrict__ bk,
    const float* __restrict__ bv, const float* __restrict__ mask, int M)
{
    extern __shared__ float sm[];
    float* Bbase = sm + NSTG * ASTAGE_F;

    const int tid  = threadIdx.x;
    const int lane = tid & 31;
    const int wid  = tid >> 5;
    const int wm   = wid >> 2;
    const int wn   = wid & 3;
    const int lr   = lane >> 2;
    const int lc   = lane & 3;

    const int m0  = blockIdx.x * 128;
    const int yb  = blockIdx.y;
    const int mat = yb / 6;
    const int n0  = (yb % 6) * 128;

    const float* Wh = g_wth + (size_t)mat * DM * DM + (size_t)n0 * DM;

    const int ak   = tid >> 3;
    const int ams  = (tid & 7) * 16;
    const float* gA = g_aht + (size_t)ak * M + m0 + ams;
    const int brow = tid >> 1;
    const int bseg = (tid & 1) * 16;
    const float* gB = Wh + (size_t)brow * DM + bseg;

    const uint32_t sbA = smem_u32(sm);
    const uint32_t sbB = smem_u32(Bbase);
    const uint32_t aXor = (uint32_t)((ak & 3) << 1);
    const uint32_t aRow = (uint32_t)ak * 512;
    const uint32_t bOff = (uint32_t)(brow * 36 + bseg) * 4;

#define ISSUE(ch, st)                                                         \
    do {                                                                      \
        const float* _a = gA + (size_t)(ch) * 32 * M;                         \
        const float* _b = gB + (ch) * 32;                                     \
        uint32_t _sa = sbA + (st) * (ASTAGE_F * 4) + aRow;                    \
        uint32_t _sb = sbB + (st) * (BSTAGE_F * 4) + bOff;                    \
        _Pragma("unroll")                                                     \
        for (int _i = 0; _i < 4; _i++) {                                      \
            uint32_t _blk = (uint32_t)((ams >> 2) + _i) ^ aXor;               \
            cpa16(_sa + _blk * 16, _a + _i * 4);                              \
            cpa16(_sb + _i * 16, _b + _i * 4);                                \
        }                                                                     \
    } while (0)

    float c[4][4][4];
#pragma unroll
    for (int i = 0; i < 4; i++)
#pragma unroll
        for (int j = 0; j < 4; j++)
#pragma unroll
            for (int q = 0; q < 4; q++) c[i][j][q] = 0.0f;

    const int NCH = DM / 32;

#pragma unroll
    for (int p = 0; p < NSTG - 1; p++) {
        ISSUE(p, p);
        cpa_commit();
    }

    for (int ch = 0; ch < NCH; ch++) {
        const int pre = ch + NSTG - 1;
        if (pre < NCH) ISSUE(pre, pre % NSTG);
        cpa_commit();
        cpa_wait<NSTG - 1>();
        __syncthreads();

        const int st = ch % NSTG;
        const float* As = sm + st * ASTAGE_F;
        const float* Bs = Bbase + st * BSTAGE_F;

#pragma unroll
        for (int ks = 0; ks < 4; ks++) {
            const int kc = ks * 8;
            uint32_t ah[4][4];
#pragma unroll
            for (int mt = 0; mt < 4; mt++) {
                const int wl = wm * 64 + mt * 16;
                const uint32_t bXor = (uint32_t)(lc << 1);
                const uint32_t blk = (uint32_t)((wl >> 2) + (lr >> 1)) ^ bXor;
                const uint32_t fo  = (uint32_t)((lr & 1) * 2);
                float2 p01 = *(const float2*)(As + (kc + lc) * 128 + blk * 4 + fo);
                float2 p23 = *(const float2*)(As + (kc + 4 + lc) * 128 + blk * 4 + fo);
                ah[mt][0] = fbits(p01.x); ah[mt][1] = fbits(p01.y);
                ah[mt][2] = fbits(p23.x); ah[mt][3] = fbits(p23.y);
            }
            uint32_t bh[4][2];
#pragma unroll
            for (int nt = 0; nt < 4; nt++) {
                const int nb = wn * 32 + nt * 8;
                bh[nt][0] = fbits(Bs[(nb + lr) * 36 + kc + lc]);
                bh[nt][1] = fbits(Bs[(nb + lr) * 36 + kc + 4 + lc]);
            }
#pragma unroll
            for (int mt = 0; mt < 4; mt++)
#pragma unroll
                for (int nt = 0; nt < 4; nt++)
                    mma8(c[mt][nt], ah[mt], bh[nt]);
        }
        __syncthreads();
    }
#undef ISSUE

    // epilogue
    const float* bias = (mat == 0) ? bq : ((mat == 1) ? bk : bv);
    float* dstqk      = (mat == 0) ? g_q : g_k;
    const bool rqk    = (mat != 2);
#pragma unroll
    for (int mt = 0; mt < 4; mt++) {
        const int m = m0 + wm * 64 + mt * 16 + lr;
#pragma unroll
        for (int nt = 0; nt < 4; nt++) {
            const int n = n0 + wn * 32 + nt * 8 + 2 * lc;
            const int hh = n >> 6, d = n & 63;
            const float b0 = bias[n], b1 = bias[n + 1];
#pragma unroll
            for (int half = 0; half < 2; half++) {
                const int mm = m + half * 8;
                const int bi = mm >> 9, srow = mm & 511;
                float v0 = c[mt][nt][half * 2 + 0] + b0;
                float v1 = c[mt][nt][half * 2 + 1] + b1;
                if (rqk) {
                    float* o = dstqk + (((size_t)(bi * NH + hh)) * SEQ + srow) * DH;
                    o[dperm(d)]     = tf32r(v0);
                    o[dperm(d + 1)] = tf32r(v1);
                } else {
                    const float mv = mask[(size_t)bi * SEQ + srow];
                    float* o = g_vt + ((size_t)(bi * NH + hh) * DH) * SEQ;
                    o[(size_t)d * SEQ + srow]       = tf32r(v0 * mv);
                    o[(size_t)(d + 1) * SEQ + srow] = tf32r(v1 * mv);
                }
            }
        }
    }
}

// ---------------------------------------------------------------------------
// Fused power-law attention.
// 8 warps x 16 q-rows (q-tile 128); key-tile 32, double-buffered cp.async.
// Q fragments live in registers for the whole kernel.
// Phase-1 accumulators feed phase-2 A-operands directly via the key-perm
// fragment mapping {c0,c2,c1,c3}; V consumed transposed [d][s] -> LDS.64.
// den = sum of (tf32-rounded, pre-mask) u, reduced across the quad at end.
// ---------------------------------------------------------------------------
#define KT 32
#define PADK 72
#define PADV 40
#define KBUF_F (KT * PADK)       // 2304
#define VBUF_F (DH * PADV)       // 2560

__global__ __launch_bounds__(256, 2) void attn_kernel(float* __restrict__ out)
{
    __shared__ float Ks[2][KBUF_F];
    __shared__ float Vs[2][VBUF_F];

    const int b  = blockIdx.z;
    const int h  = blockIdx.y;
    const int qt = blockIdx.x * 128;

    const float* Qg = g_q + (((size_t)(b * NH + h)) * SEQ + qt) * DH;
    const float* Kg = g_k + ((size_t)(b * NH + h)) * SEQ * DH;
    const float* Vg = g_vt + ((size_t)(b * NH + h)) * DH * SEQ;   // [d][s]

    const int tid  = threadIdx.x;
    const int lane = tid & 31;
    const int wid  = tid >> 5;
    const int lr   = lane >> 2;
    const int lc   = lane & 3;

    // cp.async mappings
    const int krow = tid >> 3;              // 0..31 keys
    const int ksg  = (tid & 7) * 8;         // d segment
    const float* KgR = Kg + (size_t)krow * DH + ksg;
    const uint32_t sK = smem_u32(&Ks[0][0]) + (uint32_t)(krow * PADK + ksg) * 4;

    const int vrow = tid >> 2;              // 0..63 d
    const int vsg  = (tid & 3) * 8;         // key segment
    const float* VgR = Vg + (size_t)vrow * SEQ + vsg;
    const uint32_t sV = smem_u32(&Vs[0][0]) + (uint32_t)(vrow * PADV + vsg) * 4;

#define ISSKV(kt_, buf_)                                                      \
    do {                                                                      \
        const float* _k = KgR + (size_t)(kt_) * KT * DH;                      \
        const float* _v = VgR + (kt_) * KT;                                   \
        uint32_t _ok = (uint32_t)(buf_) * (KBUF_F * 4);                       \
        uint32_t _ov = (uint32_t)(buf_) * (VBUF_F * 4);                       \
        cpa16(sK + _ok, _k);      cpa16(sK + _ok + 16, _k + 4);               \
        cpa16(sV + _ov, _v);      cpa16(sV + _ov + 16, _v + 4);               \
        cpa_commit();                                                         \
    } while (0)

    ISSKV(0, 0);

    // Q fragments: 16 rows per warp, held in registers for all tiles
    float2 qf0[8], qf1[8];
    {
        const int r0 = wid * 16 + lr;
#pragma unroll
        for (int ks = 0; ks < 8; ks++) {
            qf0[ks] = *(const float2*)(Qg + (size_t)r0 * DH + ks * 8 + 2 * lc);
            qf1[ks] = *(const float2*)(Qg + (size_t)(r0 + 8) * DH + ks * 8 + 2 * lc);
        }
    }

    float o[8][4];
#pragma unroll
    for (int j = 0; j < 8; j++)
#pragma unroll
        for (int q = 0; q < 4; q++) o[j][q] = 0.0f;
    float den0 = 0.0f, den1 = 0.0f;

    const int NKT = SEQ / KT;   // 16

    for (int kt = 0; kt < NKT; kt++) {
        const int buf = kt & 1;
        if (kt + 1 < NKT) {
            ISSKV(kt + 1, buf ^ 1);
            cpa_wait<1>();
        } else {
            cpa_wait<0>();
        }
        __syncthreads();

        const float* Kb = Ks[buf];
        const float* Vb = Vs[buf];

        // ---- phase 1: S = Q K^T ----
        float s[4][4];
#pragma unroll
        for (int j = 0; j < 4; j++)
#pragma unroll
            for (int q = 0; q < 4; q++) s[j][q] = 0.0f;

#pragma unroll
        for (int ks = 0; ks < 8; ks++) {
            uint32_t a[4];
            a[0] = fbits(qf0[ks].x); a[1] = fbits(qf1[ks].x);
            a[2] = fbits(qf0[ks].y); a[3] = fbits(qf1[ks].y);
#pragma unroll
            for (int nt = 0; nt < 4; nt++) {
                float2 k2 = *(const float2*)&Kb[(nt * 8 + lr) * PADK + ks * 8 + 2 * lc];
                uint32_t bbf[2] = {fbits(k2.x), fbits(k2.y)};
                mma8(s[nt], a, bbf);
            }
        }

        // ---- transform + phase 2 (A-frags straight from registers) ----
#pragma unroll
        for (int nt = 0; nt < 4; nt++) {
            float t0 = fmaf(s[nt][0], 0.125f, 5.0f);
            float t1 = fmaf(s[nt][1], 0.125f, 5.0f);
            float t2 = fmaf(s[nt][2], 0.125f, 5.0f);
            float t3 = fmaf(s[nt][3], 0.125f, 5.0f);
            float u0 = tf32r(t0 * t0);
            float u1 = tf32r(t1 * t1);
            float u2 = tf32r(t2 * t2);
            float u3 = tf32r(t3 * t3);
            den0 += u0 + u1;     // row lr
            den1 += u2 + u3;     // row lr+8
            uint32_t af[4] = {fbits(u0), fbits(u2), fbits(u1), fbits(u3)};
#pragma unroll
            for (int dt = 0; dt < 8; dt++) {
                float2 v2 = *(const float2*)&Vb[(dt * 8 + lr) * PADV + nt * 8 + 2 * lc];
                uint32_t bv[2] = {fbits(v2.x), fbits(v2.y)};
                mma8(o[dt], af, bv);
            }
        }
        __syncthreads();
    }
#undef ISSKV

    // quad-reduce den (lanes within quad cover disjoint key columns)
    den0 += __shfl_xor_sync(0xFFFFFFFFu, den0, 1);
    den0 += __shfl_xor_sync(0xFFFFFFFFu, den0, 2);
    den1 += __shfl_xor_sync(0xFFFFFFFFu, den1, 1);
    den1 += __shfl_xor_sync(0xFFFFFFFFu, den1, 2);

    const float inv0 = 1.0f / (den0 + 1e-10f);
    const float inv1 = 1.0f / (den1 + 1e-10f);
    const int r0 = qt + wid * 16 + lr;
    float* o0 = out + ((size_t)b * SEQ + r0) * DM + h * DH;
    float* o1 = out + ((size_t)b * SEQ + r0 + 8) * DM + h * DH;
#pragma unroll
    for (int dt = 0; dt < 8; dt++) {
        const int d = dt * 8 + 2 * lc;
        *(float2*)(o0 + d) = make_float2(o[dt][0] * inv0, o[dt][1] * inv0);
        *(float2*)(o1 + d) = make_float2(o[dt][2] * inv1, o[dt][3] * inv1);
    }
}

// ---------------------------------------------------------------------------
extern "C" void kernel_launch(void* const* d_in, const int* in_sizes, int n_in,
                              void* d_out, int out_size)
{
    const float* hidden = (const float*)d_in[0];
    const float* mask   = (const float*)d_in[1];
    const float* Wq     = (const float*)d_in[2];
    const float* bq     = (const float*)d_in[3];
    const float* Wk     = (const float*)d_in[4];
    const float* bk     = (const float*)d_in[5];
    const float* Wv     = (const float*)d_in[6];
    const float* bv     = (const float*)d_in[7];
    float* out = (float*)d_out;

    const int BS = in_sizes[1];
    const int B  = BS / SEQ;
    const int M  = BS;

    cudaFuncSetAttribute(qkv_gemm_kernel,
                         cudaFuncAttributeMaxDynamicSharedMemorySize, GEMM_SMEM);

    dim3 gh(M / 32, DM / 32);
    htrans_kernel<<<gh, dim3(32, 8)>>>(hidden, M);

    dim3 gw(DM / 32, DM / 32, 3);
    wsplit_kernel<<<gw, dim3(32, 8)>>>(Wq, Wk, Wv);

    dim3 gm(M / 128, 18);
    qkv_gemm_kernel<<<gm, 256, GEMM_SMEM>>>(bq, bk, bv, mask, M);

    dim3 g2(SEQ / 128, NH, B);
    attn_kernel<<<g2, 256>>>(out);
}